// round 2
// baseline (speedup 1.0000x reference)
#include <cuda_runtime.h>

#define NN 100000
#define EE 1200000
#define GG 128

// Scratch (device globals: no allocation anywhere)
__device__ float g_xpad[NN * 32];
__device__ float g_agg [NN * 64];
__device__ float g_mid [NN * 64];
__device__ float g_hbuf[NN * 64];

// ---------------------------------------------------------------------------
// Layer-0 prep: zero-pad x [N,30] -> xpad [N,32], and agg = (1+eps0)*xpad
// ---------------------------------------------------------------------------
__global__ void pad_init_kernel(const float* __restrict__ x,
                                const float* __restrict__ eps0,
                                float* __restrict__ xpad,
                                float* __restrict__ agg) {
    int i = blockIdx.x * blockDim.x + threadIdx.x;
    if (i >= NN * 32) return;
    int n = i >> 5, c = i & 31;
    float v = (c < 30) ? x[n * 30 + c] : 0.0f;
    float s = 1.0f + eps0[0];
    xpad[i] = v;
    agg[i]  = s * v;
}

// agg = (1+eps)*h  (vectorized)
__global__ void init_agg_kernel(const float4* __restrict__ h,
                                float4* __restrict__ agg,
                                const float* __restrict__ eps,
                                int total4) {
    int i = blockIdx.x * blockDim.x + threadIdx.x;
    if (i >= total4) return;
    float s = 1.0f + eps[0];
    float4 v = h[i];
    agg[i] = make_float4(s * v.x, s * v.y, s * v.z, s * v.w);
}

// ---------------------------------------------------------------------------
// Edge scatter: agg[dst] += h[src], chunk-parallel (2^LOGC float4-chunks/edge)
// 16 consecutive threads cover one edge's 256B row -> fully coalesced loads.
// red.global.add.v4.f32: one instruction adds 16B, no return trip.
// ---------------------------------------------------------------------------
template <int LOGC>
__global__ void scatter_kernel(const float* __restrict__ hin,
                               float* __restrict__ agg,
                               const int* __restrict__ src,
                               const int* __restrict__ dst) {
    int i = blockIdx.x * blockDim.x + threadIdx.x;
    int e = i >> LOGC;
    if (e >= EE) return;
    int c = i & ((1 << LOGC) - 1);
    const int stride = 4 << LOGC;  // 32 or 64 floats per row
    int s = src[e];
    int d = dst[e];
    const float4 v = *(const float4*)(hin + (size_t)s * stride + c * 4);
    float* p = agg + (size_t)d * stride + c * 4;
    asm volatile("red.global.add.v4.f32 [%0], {%1, %2, %3, %4};"
                 :: "l"(p), "f"(v.x), "f"(v.y), "f"(v.z), "f"(v.w)
                 : "memory");
}

// ---------------------------------------------------------------------------
// GEMM: out[n, 0:64] = (relu?)(A[n, 0:K] @ W[K,64] + bias)
// Block = 256 threads, 256 nodes/block. Thread = (output-group og of 16 cols)
// x (4 nodes strided by 64). 64 fp32 accumulators per thread -> FMA-bound.
// W staged in smem; A staged in 16-wide k-chunks (bank-conflict-free stride 20).
// ---------------------------------------------------------------------------
template <int K, bool RELU>
__global__ __launch_bounds__(256, 2) void mlp_gemm_kernel(
    const float* __restrict__ A, const float* __restrict__ W,
    const float* __restrict__ bias, float* __restrict__ out, int wRows) {
    __shared__ float w_sh[K][64];
    __shared__ float a_sh[256][20];  // stride 20: 16B aligned + conflict-free

    const int tid = threadIdx.x;
    const int og = tid & 3;        // output group: 16 columns
    const int nslot = tid >> 2;    // 0..63
    const int base = blockIdx.x * 256;

    // Stage W (zero rows >= wRows: handles 30-row w1_0 padded to K=32)
    for (int i = tid; i < K * 64; i += 256) {
        int r = i >> 6;
        w_sh[r][i & 63] = (r < wRows) ? W[i] : 0.0f;
    }

    float bv[16];
#pragma unroll
    for (int j = 0; j < 16; j++) bv[j] = bias[og * 16 + j];
    float acc[4][16];
#pragma unroll
    for (int s = 0; s < 4; s++)
#pragma unroll
        for (int j = 0; j < 16; j++) acc[s][j] = bv[j];

    for (int kc = 0; kc < K; kc += 16) {
        __syncthreads();
        // Stage 16 k-values for 256 nodes
        {
            int node = base + tid;
            float4 t0, t1, t2, t3;
            if (node < NN) {
                const float4* ap = (const float4*)(A + (size_t)node * K + kc);
                t0 = ap[0]; t1 = ap[1]; t2 = ap[2]; t3 = ap[3];
            } else {
                t0 = t1 = t2 = t3 = make_float4(0.f, 0.f, 0.f, 0.f);
            }
            *(float4*)&a_sh[tid][0]  = t0;
            *(float4*)&a_sh[tid][4]  = t1;
            *(float4*)&a_sh[tid][8]  = t2;
            *(float4*)&a_sh[tid][12] = t3;
        }
        __syncthreads();

#pragma unroll
        for (int kk = 0; kk < 16; kk++) {
            const int k = kc + kk;
            float4 w0 = *(const float4*)&w_sh[k][og * 16];
            float4 w1 = *(const float4*)&w_sh[k][og * 16 + 4];
            float4 w2 = *(const float4*)&w_sh[k][og * 16 + 8];
            float4 w3 = *(const float4*)&w_sh[k][og * 16 + 12];
#pragma unroll
            for (int s = 0; s < 4; s++) {
                float av = a_sh[nslot + s * 64][kk];
                acc[s][0]  += av * w0.x; acc[s][1]  += av * w0.y;
                acc[s][2]  += av * w0.z; acc[s][3]  += av * w0.w;
                acc[s][4]  += av * w1.x; acc[s][5]  += av * w1.y;
                acc[s][6]  += av * w1.z; acc[s][7]  += av * w1.w;
                acc[s][8]  += av * w2.x; acc[s][9]  += av * w2.y;
                acc[s][10] += av * w2.z; acc[s][11] += av * w2.w;
                acc[s][12] += av * w3.x; acc[s][13] += av * w3.y;
                acc[s][14] += av * w3.z; acc[s][15] += av * w3.w;
            }
        }
    }

#pragma unroll
    for (int s = 0; s < 4; s++) {
        int node = base + nslot + s * 64;
        if (node >= NN) continue;
        float* op = out + (size_t)node * 64 + og * 16;
#pragma unroll
        for (int q = 0; q < 4; q++) {
            float4 o;
            o.x = acc[s][q * 4 + 0];
            o.y = acc[s][q * 4 + 1];
            o.z = acc[s][q * 4 + 2];
            o.w = acc[s][q * 4 + 3];
            if (RELU) {
                o.x = fmaxf(o.x, 0.f); o.y = fmaxf(o.y, 0.f);
                o.z = fmaxf(o.z, 0.f); o.w = fmaxf(o.w, 0.f);
            }
            *(float4*)(op + q * 4) = o;
        }
    }
}

// ---------------------------------------------------------------------------
// Fused pool + final linear: out[g] = b_out + sum_{n: batch[n]=g} h[n].w_out
// ---------------------------------------------------------------------------
__global__ void out_init_kernel(float* __restrict__ out,
                                const float* __restrict__ b_out) {
    if (threadIdx.x < GG) out[threadIdx.x] = b_out[0];
}

__global__ void out_reduce_kernel(const float* __restrict__ h,
                                  const int* __restrict__ batch,
                                  const float* __restrict__ w_out,
                                  float* __restrict__ out) {
    int i = blockIdx.x * blockDim.x + threadIdx.x;
    if (i >= NN) return;
    const float4* hp = (const float4*)(h + (size_t)i * 64);
    const float4* wp = (const float4*)w_out;
    float s = 0.0f;
#pragma unroll
    for (int q = 0; q < 16; q++) {
        float4 v = hp[q];
        float4 w = wp[q];
        s += v.x * w.x + v.y * w.y + v.z * w.z + v.w * w.w;
    }
    atomicAdd(&out[batch[i]], s);
}

// ---------------------------------------------------------------------------
extern "C" void kernel_launch(void* const* d_in, const int* in_sizes, int n_in,
                              void* d_out, int out_size) {
    const float* x     = (const float*)d_in[0];
    const int*   ei    = (const int*)d_in[1];   // [2, E]
    const int*   batch = (const int*)d_in[2];
    const float* eps0  = (const float*)d_in[3];
    const float* w1_0  = (const float*)d_in[4];
    const float* b1_0  = (const float*)d_in[5];
    const float* w2_0  = (const float*)d_in[6];
    const float* b2_0  = (const float*)d_in[7];
    const float* eps_r = (const float*)d_in[8];
    const float* w1_r  = (const float*)d_in[9];
    const float* b1_r  = (const float*)d_in[10];
    const float* w2_r  = (const float*)d_in[11];
    const float* b2_r  = (const float*)d_in[12];
    const float* w_out = (const float*)d_in[13];
    const float* b_out = (const float*)d_in[14];

    const int* src = ei;
    const int* dst = ei + EE;

    float *xpad, *agg, *mid, *hbuf;
    cudaGetSymbolAddress((void**)&xpad, g_xpad);
    cudaGetSymbolAddress((void**)&agg,  g_agg);
    cudaGetSymbolAddress((void**)&mid,  g_mid);
    cudaGetSymbolAddress((void**)&hbuf, g_hbuf);

    float* outp = (float*)d_out;
    const int TB = 256;
    const int gemm_grid = (NN + 255) / 256;

    // ---- Layer 0 (K_in = 30 padded to 32) ----
    pad_init_kernel<<<(NN * 32 + TB - 1) / TB, TB>>>(x, eps0, xpad, agg);
    scatter_kernel<3><<<(EE * 8 + TB - 1) / TB, TB>>>(xpad, agg, src, dst);
    mlp_gemm_kernel<32, true ><<<gemm_grid, TB>>>(agg, w1_0, b1_0, mid, 30);
    mlp_gemm_kernel<64, false><<<gemm_grid, TB>>>(mid, w2_0, b2_0, hbuf, 64);

    // ---- Layers 1..3 ----
    for (int i = 0; i < 3; i++) {
        init_agg_kernel<<<(NN * 16 + TB - 1) / TB, TB>>>(
            (const float4*)hbuf, (float4*)agg, eps_r + i, NN * 16);
        scatter_kernel<4><<<(EE * 16 + TB - 1) / TB, TB>>>(hbuf, agg, src, dst);
        mlp_gemm_kernel<64, true ><<<gemm_grid, TB>>>(agg, w1_r + i * 4096, b1_r + i * 64, mid, 64);
        mlp_gemm_kernel<64, false><<<gemm_grid, TB>>>(mid, w2_r + i * 4096, b2_r + i * 64, hbuf, 64);
    }

    // ---- Pool + final linear (fused) ----
    out_init_kernel<<<1, 128>>>(outp, b_out);
    out_reduce_kernel<<<(NN + TB - 1) / TB, TB>>>(hbuf, batch, w_out, outp);
}

// round 4
// speedup vs baseline: 1.3417x; 1.3417x over previous
#include <cuda_runtime.h>
#include <cuda_bf16.h>
#include <cstdint>

#define NN 100000
#define EE 1200000
#define GG 128

// Scratch (device globals: no allocation anywhere)
__device__ float g_xpad[NN * 32];
__device__ float g_agg [NN * 64];
__device__ float g_hbuf[NN * 64];

// SW128-style swizzle on byte offsets within a 128B-row tile:
// XOR bits [6:4] with bits [9:7] -> conflict-free mma-fragment access.
__device__ __forceinline__ uint32_t swz(uint32_t off) {
    return off ^ ((off >> 3) & 0x70);
}

// ---------------------------------------------------------------------------
// Fused GIN MLP: out = relu(A@W1 + b1)@W2 + b2 for a 128-node tile.
// bf16 hi/lo split (3 terms) on mma.sync tensor cores, fp32 accumulate.
// A tiles: [128 rows][64 bf16 = 128B], swizzled. W tiles: Wt[n][k], 64 rows.
// ---------------------------------------------------------------------------
__device__ __forceinline__ void mma_bf16(float c[4], const uint32_t a[4],
                                         uint32_t b0, uint32_t b1) {
    asm volatile(
        "mma.sync.aligned.m16n8k16.row.col.f32.bf16.bf16.f32 "
        "{%0,%1,%2,%3}, {%4,%5,%6,%7}, {%8,%9}, {%0,%1,%2,%3};"
        : "+f"(c[0]), "+f"(c[1]), "+f"(c[2]), "+f"(c[3])
        : "r"(a[0]), "r"(a[1]), "r"(a[2]), "r"(a[3]), "r"(b0), "r"(b1));
}

__device__ __forceinline__ void split_bf16(float v, __nv_bfloat16& h, __nv_bfloat16& l) {
    h = __float2bfloat16_rn(v);
    l = __float2bfloat16_rn(v - __bfloat162float(h));
}

template <int K_IN>
__global__ __launch_bounds__(128) void fused_mlp_kernel(
    const float* __restrict__ A, const float* __restrict__ W1,
    const float* __restrict__ b1, const float* __restrict__ W2,
    const float* __restrict__ b2, float* __restrict__ out, int w1Rows) {
    __shared__ __align__(128) char sA_hi[128 * 128];  // 16KB
    __shared__ __align__(128) char sA_lo[128 * 128];  // 16KB
    __shared__ __align__(128) char sW_hi[64 * 128];   // 8KB
    __shared__ __align__(128) char sW_lo[64 * 128];   // 8KB

    const int tid  = threadIdx.x;
    const int warp = tid >> 5;
    const int lane = tid & 31;
    const int qr = lane >> 2;   // 0..7
    const int qc = lane & 3;    // 0..3
    const int base = blockIdx.x * 128;

    // ---- Stage A: [128][K_IN] fp32 -> bf16 hi/lo, swizzled, zero-pad to 64 ----
    for (int i = tid; i < 128 * 16; i += 128) {
        int row = i >> 4, chunk = i & 15;
        float4 v = make_float4(0.f, 0.f, 0.f, 0.f);
        int gn = base + row;
        if (gn < NN && chunk * 4 < K_IN)
            v = *(const float4*)(A + (size_t)gn * K_IN + chunk * 4);
        __nv_bfloat16 h[4], l[4];
        split_bf16(v.x, h[0], l[0]); split_bf16(v.y, h[1], l[1]);
        split_bf16(v.z, h[2], l[2]); split_bf16(v.w, h[3], l[3]);
        uint32_t off = swz((uint32_t)(row * 128 + chunk * 8));
        *(uint2*)(sA_hi + off) = *(uint2*)h;
        *(uint2*)(sA_lo + off) = *(uint2*)l;
    }
    // ---- Stage W1: Wt[n][k] bf16 hi/lo, zero k >= w1Rows ----
    for (int i = tid; i < 64 * 32; i += 128) {
        int n = i >> 5, c2 = i & 31;                 // c2: pair of k values
        int k0 = c2 * 2;
        float w0 = (k0     < w1Rows) ? W1[(k0    ) * 64 + n] : 0.0f;
        float w1v = (k0 + 1 < w1Rows) ? W1[(k0 + 1) * 64 + n] : 0.0f;
        __nv_bfloat16 h[2], l[2];
        split_bf16(w0, h[0], l[0]); split_bf16(w1v, h[1], l[1]);
        uint32_t off = swz((uint32_t)(n * 128 + k0 * 2));
        *(uint32_t*)(sW_hi + off) = *(uint32_t*)h;
        *(uint32_t*)(sW_lo + off) = *(uint32_t*)l;
    }
    __syncthreads();

    float c[2][8][4];
#pragma unroll
    for (int m = 0; m < 2; m++)
#pragma unroll
        for (int n = 0; n < 8; n++)
#pragma unroll
            for (int j = 0; j < 4; j++) c[m][n][j] = 0.0f;

    // ---- GEMM1: C = A @ W1 (3-term split) ----
#pragma unroll
    for (int ks = 0; ks < 4; ks++) {
        uint32_t aH[2][4], aL[2][4];
#pragma unroll
        for (int m = 0; m < 2; m++) {
            int r0 = warp * 32 + m * 16 + qr;
            int k0 = ks * 16 + qc * 2;
            aH[m][0] = *(uint32_t*)(sA_hi + swz((uint32_t)(r0 * 128 + k0 * 2)));
            aH[m][1] = *(uint32_t*)(sA_hi + swz((uint32_t)((r0 + 8) * 128 + k0 * 2)));
            aH[m][2] = *(uint32_t*)(sA_hi + swz((uint32_t)(r0 * 128 + (k0 + 8) * 2)));
            aH[m][3] = *(uint32_t*)(sA_hi + swz((uint32_t)((r0 + 8) * 128 + (k0 + 8) * 2)));
            aL[m][0] = *(uint32_t*)(sA_lo + swz((uint32_t)(r0 * 128 + k0 * 2)));
            aL[m][1] = *(uint32_t*)(sA_lo + swz((uint32_t)((r0 + 8) * 128 + k0 * 2)));
            aL[m][2] = *(uint32_t*)(sA_lo + swz((uint32_t)(r0 * 128 + (k0 + 8) * 2)));
            aL[m][3] = *(uint32_t*)(sA_lo + swz((uint32_t)((r0 + 8) * 128 + (k0 + 8) * 2)));
        }
#pragma unroll
        for (int nt = 0; nt < 8; nt++) {
            int col = nt * 8 + qr;
            int k0 = ks * 16 + qc * 2;
            uint32_t bH0 = *(uint32_t*)(sW_hi + swz((uint32_t)(col * 128 + k0 * 2)));
            uint32_t bH1 = *(uint32_t*)(sW_hi + swz((uint32_t)(col * 128 + (k0 + 8) * 2)));
            uint32_t bL0 = *(uint32_t*)(sW_lo + swz((uint32_t)(col * 128 + k0 * 2)));
            uint32_t bL1 = *(uint32_t*)(sW_lo + swz((uint32_t)(col * 128 + (k0 + 8) * 2)));
#pragma unroll
            for (int m = 0; m < 2; m++) {
                mma_bf16(c[m][nt], aH[m], bH0, bH1);
                mma_bf16(c[m][nt], aH[m], bL0, bL1);
                mma_bf16(c[m][nt], aL[m], bH0, bH1);
            }
        }
    }

    // ---- Epilogue 1: h = relu(C + b1); re-split into A tiles (own rows) ----
#pragma unroll
    for (int m = 0; m < 2; m++) {
        int r0 = warp * 32 + m * 16 + qr;
#pragma unroll
        for (int nt = 0; nt < 8; nt++) {
            int col = nt * 8 + qc * 2;
            float bv0 = __ldg(b1 + col), bv1 = __ldg(b1 + col + 1);
            float v0 = fmaxf(c[m][nt][0] + bv0, 0.0f);
            float v1 = fmaxf(c[m][nt][1] + bv1, 0.0f);
            float v2 = fmaxf(c[m][nt][2] + bv0, 0.0f);
            float v3 = fmaxf(c[m][nt][3] + bv1, 0.0f);
            __nv_bfloat16 h[2], l[2];
            split_bf16(v0, h[0], l[0]); split_bf16(v1, h[1], l[1]);
            uint32_t off = swz((uint32_t)(r0 * 128 + col * 2));
            *(uint32_t*)(sA_hi + off) = *(uint32_t*)h;
            *(uint32_t*)(sA_lo + off) = *(uint32_t*)l;
            split_bf16(v2, h[0], l[0]); split_bf16(v3, h[1], l[1]);
            off = swz((uint32_t)((r0 + 8) * 128 + col * 2));
            *(uint32_t*)(sA_hi + off) = *(uint32_t*)h;
            *(uint32_t*)(sA_lo + off) = *(uint32_t*)l;
        }
    }
    __syncthreads();  // all warps done reading W1 before restage

    // ---- Restage W2 over W1 buffers ----
    for (int i = tid; i < 64 * 32; i += 128) {
        int n = i >> 5, c2 = i & 31;
        int k0 = c2 * 2;
        float w0 = W2[k0 * 64 + n];
        float w1v = W2[(k0 + 1) * 64 + n];
        __nv_bfloat16 h[2], l[2];
        split_bf16(w0, h[0], l[0]); split_bf16(w1v, h[1], l[1]);
        uint32_t off = swz((uint32_t)(n * 128 + k0 * 2));
        *(uint32_t*)(sW_hi + off) = *(uint32_t*)h;
        *(uint32_t*)(sW_lo + off) = *(uint32_t*)l;
    }
    __syncthreads();

#pragma unroll
    for (int m = 0; m < 2; m++)
#pragma unroll
        for (int n = 0; n < 8; n++)
#pragma unroll
            for (int j = 0; j < 4; j++) c[m][n][j] = 0.0f;

    // ---- GEMM2: C = h @ W2 ----
#pragma unroll
    for (int ks = 0; ks < 4; ks++) {
        uint32_t aH[2][4], aL[2][4];
#pragma unroll
        for (int m = 0; m < 2; m++) {
            int r0 = warp * 32 + m * 16 + qr;
            int k0 = ks * 16 + qc * 2;
            aH[m][0] = *(uint32_t*)(sA_hi + swz((uint32_t)(r0 * 128 + k0 * 2)));
            aH[m][1] = *(uint32_t*)(sA_hi + swz((uint32_t)((r0 + 8) * 128 + k0 * 2)));
            aH[m][2] = *(uint32_t*)(sA_hi + swz((uint32_t)(r0 * 128 + (k0 + 8) * 2)));
            aH[m][3] = *(uint32_t*)(sA_hi + swz((uint32_t)((r0 + 8) * 128 + (k0 + 8) * 2)));
            aL[m][0] = *(uint32_t*)(sA_lo + swz((uint32_t)(r0 * 128 + k0 * 2)));
            aL[m][1] = *(uint32_t*)(sA_lo + swz((uint32_t)((r0 + 8) * 128 + k0 * 2)));
            aL[m][2] = *(uint32_t*)(sA_lo + swz((uint32_t)(r0 * 128 + (k0 + 8) * 2)));
            aL[m][3] = *(uint32_t*)(sA_lo + swz((uint32_t)((r0 + 8) * 128 + (k0 + 8) * 2)));
        }
#pragma unroll
        for (int nt = 0; nt < 8; nt++) {
            int col = nt * 8 + qr;
            int k0 = ks * 16 + qc * 2;
            uint32_t bH0 = *(uint32_t*)(sW_hi + swz((uint32_t)(col * 128 + k0 * 2)));
            uint32_t bH1 = *(uint32_t*)(sW_hi + swz((uint32_t)(col * 128 + (k0 + 8) * 2)));
            uint32_t bL0 = *(uint32_t*)(sW_lo + swz((uint32_t)(col * 128 + k0 * 2)));
            uint32_t bL1 = *(uint32_t*)(sW_lo + swz((uint32_t)(col * 128 + (k0 + 8) * 2)));
#pragma unroll
            for (int m = 0; m < 2; m++) {
                mma_bf16(c[m][nt], aH[m], bH0, bH1);
                mma_bf16(c[m][nt], aH[m], bL0, bL1);
                mma_bf16(c[m][nt], aL[m], bH0, bH1);
            }
        }
    }

    // ---- Epilogue 2: out = C + b2 -> gmem (float2 per pair, 32B sectors) ----
#pragma unroll
    for (int m = 0; m < 2; m++) {
        int r0 = warp * 32 + m * 16 + qr;
        int gn0 = base + r0, gn1 = gn0 + 8;
#pragma unroll
        for (int nt = 0; nt < 8; nt++) {
            int col = nt * 8 + qc * 2;
            float bv0 = __ldg(b2 + col), bv1 = __ldg(b2 + col + 1);
            if (gn0 < NN) {
                float2 o = make_float2(c[m][nt][0] + bv0, c[m][nt][1] + bv1);
                *(float2*)(out + (size_t)gn0 * 64 + col) = o;
            }
            if (gn1 < NN) {
                float2 o = make_float2(c[m][nt][2] + bv0, c[m][nt][3] + bv1);
                *(float2*)(out + (size_t)gn1 * 64 + col) = o;
            }
        }
    }
}

// ---------------------------------------------------------------------------
// Layer-0 prep: zero-pad x [N,30] -> xpad [N,32], and agg = (1+eps0)*xpad
// ---------------------------------------------------------------------------
__global__ void pad_init_kernel(const float* __restrict__ x,
                                const float* __restrict__ eps0,
                                float* __restrict__ xpad,
                                float* __restrict__ agg) {
    int i = blockIdx.x * blockDim.x + threadIdx.x;
    if (i >= NN * 32) return;
    int n = i >> 5, c = i & 31;
    float v = (c < 30) ? x[n * 30 + c] : 0.0f;
    float s = 1.0f + eps0[0];
    xpad[i] = v;
    agg[i]  = s * v;
}

// agg = (1+eps)*h  (vectorized)
__global__ void init_agg_kernel(const float4* __restrict__ h,
                                float4* __restrict__ agg,
                                const float* __restrict__ eps,
                                int total4) {
    int i = blockIdx.x * blockDim.x + threadIdx.x;
    if (i >= total4) return;
    float s = 1.0f + eps[0];
    float4 v = h[i];
    agg[i] = make_float4(s * v.x, s * v.y, s * v.z, s * v.w);
}

// ---------------------------------------------------------------------------
// Edge scatter: agg[dst] += h[src], chunk-parallel (2^LOGC float4-chunks/edge)
// ---------------------------------------------------------------------------
template <int LOGC>
__global__ void scatter_kernel(const float* __restrict__ hin,
                               float* __restrict__ agg,
                               const int* __restrict__ src,
                               const int* __restrict__ dst) {
    int i = blockIdx.x * blockDim.x + threadIdx.x;
    int e = i >> LOGC;
    if (e >= EE) return;
    int c = i & ((1 << LOGC) - 1);
    const int stride = 4 << LOGC;  // 32 or 64 floats per row
    int s = src[e];
    int d = dst[e];
    const float4 v = *(const float4*)(hin + (size_t)s * stride + c * 4);
    float* p = agg + (size_t)d * stride + c * 4;
    asm volatile("red.global.add.v4.f32 [%0], {%1, %2, %3, %4};"
                 :: "l"(p), "f"(v.x), "f"(v.y), "f"(v.z), "f"(v.w)
                 : "memory");
}

// ---------------------------------------------------------------------------
// Fused pool + final linear
// ---------------------------------------------------------------------------
__global__ void out_init_kernel(float* __restrict__ out,
                                const float* __restrict__ b_out) {
    if (threadIdx.x < GG) out[threadIdx.x] = b_out[0];
}

__global__ void out_reduce_kernel(const float* __restrict__ h,
                                  const int* __restrict__ batch,
                                  const float* __restrict__ w_out,
                                  float* __restrict__ out) {
    int i = blockIdx.x * blockDim.x + threadIdx.x;
    if (i >= NN) return;
    const float4* hp = (const float4*)(h + (size_t)i * 64);
    const float4* wp = (const float4*)w_out;
    float s = 0.0f;
#pragma unroll
    for (int q = 0; q < 16; q++) {
        float4 v = hp[q];
        float4 w = wp[q];
        s += v.x * w.x + v.y * w.y + v.z * w.z + v.w * w.w;
    }
    atomicAdd(&out[batch[i]], s);
}

// ---------------------------------------------------------------------------
extern "C" void kernel_launch(void* const* d_in, const int* in_sizes, int n_in,
                              void* d_out, int out_size) {
    const float* x     = (const float*)d_in[0];
    const int*   ei    = (const int*)d_in[1];   // [2, E]
    const int*   batch = (const int*)d_in[2];
    const float* eps0  = (const float*)d_in[3];
    const float* w1_0  = (const float*)d_in[4];
    const float* b1_0  = (const float*)d_in[5];
    const float* w2_0  = (const float*)d_in[6];
    const float* b2_0  = (const float*)d_in[7];
    const float* eps_r = (const float*)d_in[8];
    const float* w1_r  = (const float*)d_in[9];
    const float* b1_r  = (const float*)d_in[10];
    const float* w2_r  = (const float*)d_in[11];
    const float* b2_r  = (const float*)d_in[12];
    const float* w_out = (const float*)d_in[13];
    const float* b_out = (const float*)d_in[14];

    const int* src = ei;
    const int* dst = ei + EE;

    float *xpad, *agg, *hbuf;
    cudaGetSymbolAddress((void**)&xpad, g_xpad);
    cudaGetSymbolAddress((void**)&agg,  g_agg);
    cudaGetSymbolAddress((void**)&hbuf, g_hbuf);

    float* outp = (float*)d_out;
    const int TB = 256;
    const int mlp_grid = (NN + 127) / 128;

    // ---- Layer 0 (K_in = 30 padded to 32) ----
    pad_init_kernel<<<(NN * 32 + TB - 1) / TB, TB>>>(x, eps0, xpad, agg);
    scatter_kernel<3><<<(EE * 8 + TB - 1) / TB, TB>>>(xpad, agg, src, dst);
    fused_mlp_kernel<32><<<mlp_grid, 128>>>(agg, w1_0, b1_0, w2_0, b2_0, hbuf, 30);

    // ---- Layers 1..3 ----
    for (int i = 0; i < 3; i++) {
        init_agg_kernel<<<(NN * 16 + TB - 1) / TB, TB>>>(
            (const float4*)hbuf, (float4*)agg, eps_r + i, NN * 16);
        scatter_kernel<4><<<(EE * 16 + TB - 1) / TB, TB>>>(hbuf, agg, src, dst);
        fused_mlp_kernel<64><<<mlp_grid, 128>>>(agg, w1_r + i * 4096, b1_r + i * 64,
                                                w2_r + i * 4096, b2_r + i * 64, hbuf, 64);
    }

    // ---- Pool + final linear (fused) ----
    out_init_kernel<<<1, 128>>>(outp, b_out);
    out_reduce_kernel<<<(NN + TB - 1) / TB, TB>>>(hbuf, batch, w_out, outp);
}